// round 6
// baseline (speedup 1.0000x reference)
#include <cuda_runtime.h>
#include <cuda_fp16.h>
#include <cstdint>

#define NBX 512
#define NBY 512
#define NMAX 5000000
#define ITEMS 8

// fp16-packed 2x2 neighborhood of utilization_map (2 MB):
// entry[bx*NBY+by] = { h2(u00,u01), h2(u10,u11) }
__device__ __align__(8) uint2 g_packu[NBX * NBY];
// membership mask for the scatter semantics: out[p] = flag[p] ? area(p) : 0.
// Zero-initialized at load; every call sets (setup) then fully clears (main).
__device__ unsigned char g_flag[NMAX];

// Combined setup: build flag from idx + pack the utilization map.
__global__ __launch_bounds__(256)
void setup_kernel(const int* __restrict__ idx, int nidx, int n,
                  const float* __restrict__ umap)
{
    int k = blockIdx.x * blockDim.x + threadIdx.x;
    if (k < nidx) {
        int p = __ldg(&idx[k]);
        if (p >= 0 && p < n) g_flag[p] = 1;
    }
    if (k < NBX * NBY) {
        int bx = k / NBY;
        int by = k % NBY;
        int by1 = min(by + 1, NBY - 1);
        int bx1 = min(bx + 1, NBX - 1);
        float u00 = __ldg(&umap[bx  * NBY + by ]);
        float u01 = __ldg(&umap[bx  * NBY + by1]);
        float u10 = __ldg(&umap[bx1 * NBY + by ]);
        float u11 = __ldg(&umap[bx1 * NBY + by1]);
        __half2 a = __floats2half2_rn(u00, u01);
        __half2 b = __floats2half2_rn(u10, u11);
        uint2 pk;
        pk.x = *reinterpret_cast<unsigned int*>(&a);
        pk.y = *reinterpret_cast<unsigned int*>(&b);
        g_packu[k] = pk;
    }
}

__global__ __launch_bounds__(256, 4)
void route_area_kernel(const float* __restrict__ pos,
                       const float* __restrict__ sx,
                       const float* __restrict__ sy,
                       float*       __restrict__ out,
                       int n)
{
    const int p0 = (blockIdx.x * blockDim.x + threadIdx.x) * ITEMS;
    if (p0 >= n) return;

    float x[ITEMS], y[ITEMS], w[ITEMS], h[ITEMS];
    uint2 uu[ITEMS];
    float area[ITEMS];

    if (p0 + ITEMS <= n) {
        // ---- fast path: fully dense, vectorized ----
        // Phase A: x, y via float4 (gather address depends only on these)
        const float4* px4 = reinterpret_cast<const float4*>(pos + p0);
        const float4* py4 = reinterpret_cast<const float4*>(pos + n + p0);
        #pragma unroll
        for (int v = 0; v < ITEMS / 4; v++) {
            float4 vx = __ldcs(&px4[v]);
            float4 vy = __ldcs(&py4[v]);
            x[v*4+0] = vx.x; x[v*4+1] = vx.y; x[v*4+2] = vx.z; x[v*4+3] = vx.w;
            y[v*4+0] = vy.x; y[v*4+1] = vy.y; y[v*4+2] = vy.z; y[v*4+3] = vy.w;
        }

        // Phase B: shortest chain to the gathers; all issue back-to-back
        #pragma unroll
        for (int i = 0; i < ITEMS; i++) {
            int bx0 = min(max((int)floorf(x[i]), 0), NBX - 1);
            int by0 = min(max((int)floorf(y[i]), 0), NBY - 1);
            uu[i] = __ldg(&g_packu[bx0 * NBY + by0]);
        }

        // Phase C: w, h + flag loads run concurrently with the gathers
        const float4* pw4 = reinterpret_cast<const float4*>(sx + p0);
        const float4* ph4 = reinterpret_cast<const float4*>(sy + p0);
        #pragma unroll
        for (int v = 0; v < ITEMS / 4; v++) {
            float4 vw = __ldcs(&pw4[v]);
            float4 vh = __ldcs(&ph4[v]);
            w[v*4+0] = vw.x; w[v*4+1] = vw.y; w[v*4+2] = vw.z; w[v*4+3] = vw.w;
            h[v*4+0] = vh.x; h[v*4+1] = vh.y; h[v*4+2] = vh.z; h[v*4+3] = vh.w;
        }
        uint2 fl = *reinterpret_cast<const uint2*>(&g_flag[p0]);   // 8 flag bytes

        // Phase D: overlap math
        #pragma unroll
        for (int i = 0; i < ITEMS; i++) {
            float xh = x[i] + w[i];
            float yh = y[i] + h[i];
            int bx0 = min(max((int)floorf(x[i]), 0), NBX - 1);
            int by0 = min(max((int)floorf(y[i]), 0), NBY - 1);
            float fbx0 = (float)bx0;
            float fby0 = (float)by0;

            float ox0 = fmaxf(fminf(xh, fbx0 + 1.0f) - fmaxf(x[i], fbx0), 0.0f);
            float ox1 = fmaxf(fminf(xh, fbx0 + 2.0f) - fmaxf(x[i], fbx0 + 1.0f), 0.0f);
            if (bx0 + 1 >= NBX) ox1 = 0.0f;

            float oy0 = fmaxf(fminf(yh, fby0 + 1.0f) - fmaxf(y[i], fby0), 0.0f);
            float oy1 = fmaxf(fminf(yh, fby0 + 2.0f) - fmaxf(y[i], fby0 + 1.0f), 0.0f);
            if (by0 + 1 >= NBY) oy1 = 0.0f;

            __half2 ha = *reinterpret_cast<__half2*>(&uu[i].x);
            __half2 hb = *reinterpret_cast<__half2*>(&uu[i].y);
            float2 f0 = __half22float2(ha);
            float2 f1 = __half22float2(hb);

            float a0 = ox0 * oy0 * f0.x;
            a0 += ox0 * oy1 * f0.y;
            a0 += ox1 * oy0 * f1.x;
            a0 += ox1 * oy1 * f1.y;

            unsigned int fb = (i < 4) ? (fl.x >> (i * 8)) : (fl.y >> ((i - 4) * 8));
            area[i] = (fb & 0xFF) ? a0 : 0.0f;
        }

        // Phase E: vectorized stores + clear flags (for the next replay)
        float4* po4 = reinterpret_cast<float4*>(out + p0);
        #pragma unroll
        for (int v = 0; v < ITEMS / 4; v++) {
            float4 vo;
            vo.x = area[v*4+0]; vo.y = area[v*4+1];
            vo.z = area[v*4+2]; vo.w = area[v*4+3];
            po4[v] = vo;
        }
        uint2 z; z.x = 0u; z.y = 0u;
        *reinterpret_cast<uint2*>(&g_flag[p0]) = z;
    } else {
        // ---- tail path (only if n % ITEMS != 0) ----
        for (int p = p0; p < n; p++) {
            float xx = pos[p], yy = pos[p + n];
            float ww = sx[p], hh = sy[p];
            float xh = xx + ww, yh = yy + hh;
            int bx0 = min(max((int)floorf(xx), 0), NBX - 1);
            int by0 = min(max((int)floorf(yy), 0), NBY - 1);
            float fbx0 = (float)bx0, fby0 = (float)by0;

            float ox0 = fmaxf(fminf(xh, fbx0 + 1.0f) - fmaxf(xx, fbx0), 0.0f);
            float ox1 = fmaxf(fminf(xh, fbx0 + 2.0f) - fmaxf(xx, fbx0 + 1.0f), 0.0f);
            if (bx0 + 1 >= NBX) ox1 = 0.0f;
            float oy0 = fmaxf(fminf(yh, fby0 + 1.0f) - fmaxf(yy, fby0), 0.0f);
            float oy1 = fmaxf(fminf(yh, fby0 + 2.0f) - fmaxf(yy, fby0 + 1.0f), 0.0f);
            if (by0 + 1 >= NBY) oy1 = 0.0f;

            uint2 u = g_packu[bx0 * NBY + by0];
            __half2 ha = *reinterpret_cast<__half2*>(&u.x);
            __half2 hb = *reinterpret_cast<__half2*>(&u.y);
            float2 f0 = __half22float2(ha);
            float2 f1 = __half22float2(hb);

            float a0 = ox0 * oy0 * f0.x + ox0 * oy1 * f0.y
                     + ox1 * oy0 * f1.x + ox1 * oy1 * f1.y;
            out[p] = g_flag[p] ? a0 : 0.0f;
            g_flag[p] = 0;
        }
    }
}

extern "C" void kernel_launch(void* const* d_in, const int* in_sizes, int n_in,
                              void* d_out, int out_size)
{
    const float* pos  = (const float*)d_in[0];
    const float* sx   = (const float*)d_in[1];
    const float* sy   = (const float*)d_in[2];
    const float* umap = (const float*)d_in[3];
    const int*   idx  = (const int*)d_in[4];
    float* out = (float*)d_out;

    const int n    = in_sizes[1];   // N nodes (pos has 2N)
    const int nidx = in_sizes[4];

    // Setup: flag[idx[k]] = 1 and pack the umap. (flag is all-zero on entry:
    // zero-initialized at load, and the main kernel clears it every call.)
    {
        int work = max(nidx, NBX * NBY);
        setup_kernel<<<(work + 255) / 256, 256>>>(idx, nidx, n, umap);
    }

    const int threads = 256;
    const int per_grid = threads * ITEMS;
    int blocks = (n + per_grid - 1) / per_grid;
    route_area_kernel<<<blocks, threads>>>(pos, sx, sy, out, n);
}

// round 7
// speedup vs baseline: 1.3692x; 1.3692x over previous
#include <cuda_runtime.h>
#include <cuda_fp16.h>
#include <cstdint>

#define NBX 512
#define NBY 512
#define ITEMS 8

// fp16-packed 2x2 neighborhood of utilization_map (2 MB):
// entry[bx*NBY+by] = { h2(u00,u01), h2(u10,u11) }
__device__ __align__(8) uint2 g_packu[NBX * NBY];

// Fused setup: pack the umap (first 1024 blocks) + zero `out` (all blocks).
// Launched with enough blocks to cover out_size/4 float4 stores.
__global__ __launch_bounds__(256)
void setup_kernel(const float* __restrict__ umap,
                  float4* __restrict__ out4, int nout4, float* __restrict__ out,
                  int nout)
{
    int t = blockIdx.x * blockDim.x + threadIdx.x;

    // Pack table: 512*512 = 262144 entries = first 1024 blocks.
    if (t < NBX * NBY) {
        int bx = t / NBY;
        int by = t % NBY;
        int by1 = min(by + 1, NBY - 1);
        int bx1 = min(bx + 1, NBX - 1);
        float u00 = __ldg(&umap[bx  * NBY + by ]);
        float u01 = __ldg(&umap[bx  * NBY + by1]);
        float u10 = __ldg(&umap[bx1 * NBY + by ]);
        float u11 = __ldg(&umap[bx1 * NBY + by1]);
        __half2 a = __floats2half2_rn(u00, u01);
        __half2 b = __floats2half2_rn(u10, u11);
        uint2 pk;
        pk.x = *reinterpret_cast<unsigned int*>(&a);
        pk.y = *reinterpret_cast<unsigned int*>(&b);
        g_packu[t] = pk;
    }

    // Zero out[] with 16B stores.
    if (t < nout4) {
        float4 z; z.x = 0.f; z.y = 0.f; z.z = 0.f; z.w = 0.f;
        out4[t] = z;
    }
    // Scalar tail (if out_size % 4 != 0).
    int tail = nout4 * 4 + t;
    if (tail < nout) out[tail] = 0.0f;
}

__global__ __launch_bounds__(256, 4)
void route_area_kernel(const float* __restrict__ pos,
                       const float* __restrict__ sx,
                       const float* __restrict__ sy,
                       const int*   __restrict__ idx,
                       float*       __restrict__ out,
                       int n, int nidx)
{
    const int t = blockIdx.x * blockDim.x + threadIdx.x;
    const int S = gridDim.x * blockDim.x;

    int   j[ITEMS];
    float x[ITEMS], y[ITEMS];
    float w[ITEMS], h[ITEMS];
    uint2 uu[ITEMS];
    int   bx0[ITEMS], by0[ITEMS];

    // Phase A: index loads (coalesced). j = -1 marks inactive.
    #pragma unroll
    for (int i = 0; i < ITEMS; i++) {
        int k = t + i * S;
        j[i] = (k < nidx) ? __ldg(&idx[k]) : -1;
    }

    // Phase B: x, y loads only — the gather address depends only on these.
    #pragma unroll
    for (int i = 0; i < ITEMS; i++) {
        int jj = (j[i] >= 0) ? j[i] : 0;
        x[i] = __ldcs(&pos[jj]);
        y[i] = __ldcs(&pos[jj + n]);
    }

    // Phase C: shortest chain to the gathers; all 8 issue back-to-back.
    #pragma unroll
    for (int i = 0; i < ITEMS; i++) {
        bx0[i] = min(max((int)floorf(x[i]), 0), NBX - 1);
        by0[i] = min(max((int)floorf(y[i]), 0), NBY - 1);
        uu[i] = __ldg(&g_packu[bx0[i] * NBY + by0[i]]);
    }

    // Phase D: w, h loads — latency runs concurrently with the gathers.
    #pragma unroll
    for (int i = 0; i < ITEMS; i++) {
        int jj = (j[i] >= 0) ? j[i] : 0;
        w[i] = __ldcs(&sx[jj]);
        h[i] = __ldcs(&sy[jj]);
    }

    // Phase E: overlap math + unpack + scatter store.
    #pragma unroll
    for (int i = 0; i < ITEMS; i++) {
        float xh = x[i] + w[i];
        float yh = y[i] + h[i];
        float fbx0 = (float)bx0[i];
        float fby0 = (float)by0[i];

        float ox0 = fmaxf(fminf(xh, fbx0 + 1.0f) - fmaxf(x[i], fbx0), 0.0f);
        float ox1 = fmaxf(fminf(xh, fbx0 + 2.0f) - fmaxf(x[i], fbx0 + 1.0f), 0.0f);
        if (bx0[i] + 1 >= NBX) ox1 = 0.0f;

        float oy0 = fmaxf(fminf(yh, fby0 + 1.0f) - fmaxf(y[i], fby0), 0.0f);
        float oy1 = fmaxf(fminf(yh, fby0 + 2.0f) - fmaxf(y[i], fby0 + 1.0f), 0.0f);
        if (by0[i] + 1 >= NBY) oy1 = 0.0f;

        __half2 ha = *reinterpret_cast<__half2*>(&uu[i].x);
        __half2 hb = *reinterpret_cast<__half2*>(&uu[i].y);
        float2 f0 = __half22float2(ha);   // (u00, u01)
        float2 f1 = __half22float2(hb);   // (u10, u11)

        float area = ox0 * oy0 * f0.x;
        area += ox0 * oy1 * f0.y;
        area += ox1 * oy0 * f1.x;
        area += ox1 * oy1 * f1.y;

        if (j[i] >= 0) out[j[i]] = area;
    }
}

extern "C" void kernel_launch(void* const* d_in, const int* in_sizes, int n_in,
                              void* d_out, int out_size)
{
    const float* pos  = (const float*)d_in[0];
    const float* sx   = (const float*)d_in[1];
    const float* sy   = (const float*)d_in[2];
    const float* umap = (const float*)d_in[3];
    const int*   idx  = (const int*)d_in[4];
    float* out = (float*)d_out;

    const int n    = in_sizes[1];   // N nodes (pos has 2N)
    const int nidx = in_sizes[4];

    // Fused setup: zero out[] (16B stores) + pack the umap, one kernel.
    {
        int nout4 = out_size / 4;
        int work = nout4 > (NBX * NBY) ? nout4 : (NBX * NBY);
        // +256 threads to also cover the scalar tail positions.
        int blocks = (work + 255) / 256 + 1;
        setup_kernel<<<blocks, 256>>>(umap, (float4*)out, nout4, out, out_size);
    }

    const int threads = 256;
    const int per_grid = threads * ITEMS;
    int blocks = (nidx + per_grid - 1) / per_grid;
    route_area_kernel<<<blocks, threads>>>(pos, sx, sy, idx, out, n, nidx);
}